// round 14
// baseline (speedup 1.0000x reference)
#include <cuda_runtime.h>

#define NB      32768
#define SLOTS   8

__device__ float g_score[64];

typedef unsigned long long u64;
typedef unsigned int u32;

__device__ u64 g_B1h[2048];       // [E1;Q1] hi-bf16 B-frags [tile=kt*8+nt][lane], K=128
__device__ u64 g_B1l[2048];
__device__ u64 g_B2h[1024];       // W2 hi-bf16 B-frags, K=64
__device__ u64 g_B2l[1024];

#define CVTP(d, fhi, flo)  asm("cvt.rn.bf16x2.f32 %0, %1, %2;" : "=r"(d) : "f"(fhi), "f"(flo))
#define MMA4(d0,d1,d2,d3,a0,a1,a2,a3,b0,b1) \
    asm("mma.sync.aligned.m16n8k16.row.col.f32.bf16.bf16.f32 " \
        "{%0,%1,%2,%3},{%4,%5,%6,%7},{%8,%9},{%0,%1,%2,%3};" \
        : "+f"(d0),"+f"(d1),"+f"(d2),"+f"(d3) \
        : "r"(a0),"r"(a1),"r"(a2),"r"(a3),"r"(b0),"r"(b1))

// smem layout (bytes) for main_k
#define OFF_B1H  0          // u64[2048] = 16384
#define OFF_B1L  16384      // u64[2048] = 16384
#define OFF_B2H  32768      // u64[1024] = 8192
#define OFF_B2L  40960      // u64[1024] = 8192
#define OFF_CNT  49152      // u32[128*12] = 6144
#define OFF_SC   55296      // float[64]
#define OFF_B2V  55552      // float[64]
#define OFF_RK   55808      // u32[64]
#define OFF_Q    56064      // int[128]
#define SMEM_TOTAL 56576

static __device__ __forceinline__ void split_pack(
    float f00, float f01, float f10, float f11, u64* ph, u64* pl)
{
    u32 b0h, b1h, b0l, b1l;
    CVTP(b0h, f01, f00);
    CVTP(b1h, f11, f10);
    const float h00 = __uint_as_float(b0h << 16), h01 = __uint_as_float(b0h & 0xFFFF0000u);
    const float h10 = __uint_as_float(b1h << 16), h11 = __uint_as_float(b1h & 0xFFFF0000u);
    CVTP(b0l, f01 - h01, f00 - h00);
    CVTP(b1l, f11 - h11, f10 - h10);
    *ph = (u64)b0h | ((u64)b1h << 32);
    *pl = (u64)b0l | ((u64)b1l << 32);
}

// ---------------------------------------------------------------------------
// prep_k: ONE kernel for all precompute.
//  blocks 0-7 : B1 fragments for kt tile (compute 16 stacked [E1;Q1] rows, emit)
//  blocks 8-9 : B2 fragments from w2
//  block  10  : score table
// ---------------------------------------------------------------------------
__global__ void __launch_bounds__(256) prep_k(
    const float* __restrict__ emb,
    const float* __restrict__ sw1, const float* __restrict__ sb1,
    const float* __restrict__ sw2, const float* __restrict__ sb2,
    const float* __restrict__ w1,  const float* __restrict__ b1,
    const float* __restrict__ w2)
{
    __shared__ float sbuf[64 * 64];          // 16KB
    const int tid = threadIdx.x;
    const int b   = blockIdx.x;

    if (b < 8) {
        // ---- B1 fragments for kt = b ----
        float* s_emb = sbuf;                 // [16][64]
        float* s_tab = sbuf + 1024;          // [16][64]
        const int kt = b;
        const int base_tok = (kt < 4) ? kt * 16 : (kt - 4) * 16;
        ((float4*)s_emb)[tid] = ((const float4*)(emb + base_tok * 64))[tid];
        __syncthreads();

        {
            const int r = tid >> 4, n0 = (tid & 15) * 4;
            const int off = (kt < 4) ? 64 : 0;   // E1 half uses w1[64+d], Q1 half w1[d]
            float a0 = 0.f, a1 = 0.f, a2 = 0.f, a3 = 0.f;
#pragma unroll 8
            for (int d = 0; d < 64; d++) {
                const float e = s_emb[r * 64 + d];
                const float4 wv = *(const float4*)(w1 + (off + d) * 64 + n0);
                a0 = fmaf(e, wv.x, a0); a1 = fmaf(e, wv.y, a1);
                a2 = fmaf(e, wv.z, a2); a3 = fmaf(e, wv.w, a3);
            }
            if (kt < 4) { a0 *= 0.125f; a1 *= 0.125f; a2 *= 0.125f; a3 *= 0.125f; }
            else { a0 += b1[n0]; a1 += b1[n0 + 1]; a2 += b1[n0 + 2]; a3 += b1[n0 + 3]; }
            float* tp = s_tab + r * 64 + n0;
            tp[0] = a0; tp[1] = a1; tp[2] = a2; tp[3] = a3;
        }
        __syncthreads();

        {
            const int l  = tid & 31;
            const int lr = (l & 3) * 2;
            const int n  = (tid >> 5) * 8 + (l >> 2);
            const int e  = kt * 256 + tid;
            split_pack(s_tab[lr * 64 + n],       s_tab[(lr + 1) * 64 + n],
                       s_tab[(lr + 8) * 64 + n], s_tab[(lr + 9) * 64 + n],
                       &g_B1h[e], &g_B1l[e]);
        }
        return;
    }

    if (b < 10) {
        // ---- B2 fragments (r13 mapping verbatim) ----
#pragma unroll
        for (int j = 0; j < 2; j++) {
            const int e = (b - 8) * 512 + tid * 2 + j;
            const int tile = e >> 5, l = e & 31;
            const int kt = tile >> 3, nt = tile & 7;
            const int k0 = kt * 16 + (l & 3) * 2;
            const int n  = nt * 8 + (l >> 2);
            split_pack(w2[k0 * 64 + n], w2[(k0 + 1) * 64 + n],
                       w2[(k0 + 8) * 64 + n], w2[(k0 + 9) * 64 + n],
                       &g_B2h[e], &g_B2l[e]);
        }
        return;
    }

    // ---- block 10: score table ----
#pragma unroll
    for (int i = tid; i < 1024; i += 256)
        ((float4*)sbuf)[i] = ((const float4*)emb)[i];
    __syncthreads();
    {
        const int tok = tid >> 2, p = tid & 3;
        float acc[8];
#pragma unroll
        for (int h = 0; h < 8; h++) acc[h] = sb1[p * 8 + h];
#pragma unroll 4
        for (int d = 0; d < 64; d++) {
            const float e = sbuf[tok * 64 + d];
            const float4 wa = *(const float4*)(sw1 + d * 32 + p * 8);
            const float4 wb = *(const float4*)(sw1 + d * 32 + p * 8 + 4);
            acc[0] = fmaf(e, wa.x, acc[0]); acc[1] = fmaf(e, wa.y, acc[1]);
            acc[2] = fmaf(e, wa.z, acc[2]); acc[3] = fmaf(e, wa.w, acc[3]);
            acc[4] = fmaf(e, wb.x, acc[4]); acc[5] = fmaf(e, wb.y, acc[5]);
            acc[6] = fmaf(e, wb.z, acc[6]); acc[7] = fmaf(e, wb.w, acc[7]);
        }
        float s = 0.f;
#pragma unroll
        for (int h = 0; h < 8; h++) s += fmaxf(acc[h], 0.f) * sw2[p * 8 + h];
        s += __shfl_down_sync(0xffffffffu, s, 2, 4);
        s += __shfl_down_sync(0xffffffffu, s, 1, 4);
        if (p == 0) g_score[tok] = s + sb2[0];
    }
}

// ---------------------------------------------------------------------------
// main_k: identical to round-13 passing version.
// ---------------------------------------------------------------------------
__global__ void __launch_bounds__(256, 2) main_k(
    const int*   __restrict__ seqs,
    const int*   __restrict__ qtok,
    const float* __restrict__ b2,
    float*       __restrict__ out)
{
    extern __shared__ __align__(16) char dyn[];
    u64*   s_B1h = (u64*)(dyn + OFF_B1H);
    u64*   s_B1l = (u64*)(dyn + OFF_B1L);
    u64*   s_B2h = (u64*)(dyn + OFF_B2H);
    u64*   s_B2l = (u64*)(dyn + OFF_B2L);
    u32*   s_cnt = (u32*)(dyn + OFF_CNT);
    float* s_sc  = (float*)(dyn + OFF_SC);
    float* s_b2  = (float*)(dyn + OFF_B2V);
    u32*   s_rk  = (u32*)(dyn + OFF_RK);
    int*   s_q   = (int*)(dyn + OFF_Q);

    const int tid  = threadIdx.x;
    const int lane = tid & 31;
    const int wrp  = tid >> 5;

    if (tid < 64) { s_sc[tid] = g_score[tid]; s_b2[tid] = b2[tid]; }
    __syncthreads();

    if (tid < 64) {
        const float st = s_sc[tid];
        int r = 0;
#pragma unroll 16
        for (int u = 0; u < 64; u++) r += (s_sc[u] < st);
        s_rk[tid] = ((u32)r << 11) | (u32)tid;
    } else {
        const int t2 = tid - 64;
        const ulonglong2* gB1h = (const ulonglong2*)g_B1h;
        const ulonglong2* gB1l = (const ulonglong2*)g_B1l;
        const ulonglong2* gB2h = (const ulonglong2*)g_B2h;
        const ulonglong2* gB2l = (const ulonglong2*)g_B2l;
#pragma unroll
        for (int i = t2; i < 1024; i += 192) {
            ((ulonglong2*)s_B1h)[i] = gB1h[i];
            ((ulonglong2*)s_B1l)[i] = gB1l[i];
        }
        for (int i = t2; i < 512; i += 192) {
            ((ulonglong2*)s_B2h)[i] = gB2h[i];
            ((ulonglong2*)s_B2l)[i] = gB2l[i];
        }
    }
    __syncthreads();

    if (tid < 128) {
        const int item = blockIdx.x * 128 + tid;
        const int4* sp = (const int4*)seqs + item * 8;
        u32 w8[8];
#pragma unroll
        for (int g = 0; g < 8; g++) {
            const int4 v = sp[g];
            w8[g] = (u32)(v.x & 63) | ((u32)(v.y & 63) << 8) |
                    ((u32)(v.z & 63) << 16) | ((u32)(v.w & 63) << 24);
        }
        u32 k31[31];
#pragma unroll
        for (int j = 0; j < 31; j++) {
            const u32 t = (w8[j >> 2] >> ((j & 3) * 8)) & 63u;
            k31[j] = s_rk[t] + ((u32)j << 6);
        }
        u32 key[SLOTS];
#pragma unroll
        for (int j = 0; j < SLOTS; j++) key[j] = k31[j];
#pragma unroll
        for (int step = 8; step < 31; step++) {
            const u32 m01 = umin(key[0], key[1]);
            const u32 m23 = umin(key[2], key[3]);
            const u32 m45 = umin(key[4], key[5]);
            const u32 m67 = umin(key[6], key[7]);
            const u32 mk  = umin(umin(m01, m23), umin(m45, m67));
            const u32 nk  = k31[step];
#pragma unroll
            for (int j = 0; j < SLOTS; j++)
                key[j] = (key[j] == mk) ? nk : key[j];
        }
        u32 cnt[8] = {0, 0, 0, 0, 0, 0, 0, 0};
#pragma unroll
        for (int s = 0; s < SLOTS; s++) {
            const u32 tok = key[s] & 63u;
            const u32 inc = 1u << ((tok & 7u) * 4);
            const u32 w   = tok >> 3;
#pragma unroll
            for (int j = 0; j < 8; j++)
                if (w == (u32)j) cnt[j] += inc;
        }
        u32* cp = s_cnt + tid * 12;
        *(uint4*)(cp)     = make_uint4(cnt[0], cnt[1], cnt[2], cnt[3]);
        *(uint4*)(cp + 4) = make_uint4(cnt[4], cnt[5], cnt[6], cnt[7]);
        s_q[tid] = qtok[item] & 63;
    }
    __syncthreads();

    // layer1 GEMM: (counts || onehot) @ [E1;Q1]
    const int r0i = wrp * 16 + (lane >> 2);
    u32 A1[32];
    {
        const u32* c0p = s_cnt + r0i * 12;
        const u32* c1p = s_cnt + (r0i + 8) * 12;
        uint4 a4 = *(const uint4*)(c0p), b4 = *(const uint4*)(c0p + 4);
        uint4 c4 = *(const uint4*)(c1p), d4 = *(const uint4*)(c1p + 4);
        const u32 wA[8] = {a4.x, a4.y, a4.z, a4.w, b4.x, b4.y, b4.z, b4.w};
        const u32 wB[8] = {c4.x, c4.y, c4.z, c4.w, d4.x, d4.y, d4.z, d4.w};
        const int q0 = s_q[r0i], q1 = s_q[r0i + 8];
        const int sh = (lane & 3) * 8;
#define NIB2BF(dst, word) do { \
            const u32 _b = ((word) >> sh) & 0xFFu; \
            const float _lo = (float)(_b & 15u), _hi = (float)(_b >> 4); \
            CVTP(dst, _hi, _lo); } while (0)
#pragma unroll
        for (int kt = 0; kt < 4; kt++) {
            NIB2BF(A1[4 * kt + 0], wA[2 * kt]);
            NIB2BF(A1[4 * kt + 1], wB[2 * kt]);
            NIB2BF(A1[4 * kt + 2], wA[2 * kt + 1]);
            NIB2BF(A1[4 * kt + 3], wB[2 * kt + 1]);
        }
        const int j00 = (lane & 3) * 2;
#pragma unroll
        for (int kt = 4; kt < 8; kt++) {
            const int jb = (kt - 4) * 16 + j00;
            A1[4 * kt + 0] = (q0 == jb     ? 0x3F80u : 0u) | (q0 == jb + 1 ? 0x3F800000u : 0u);
            A1[4 * kt + 1] = (q1 == jb     ? 0x3F80u : 0u) | (q1 == jb + 1 ? 0x3F800000u : 0u);
            A1[4 * kt + 2] = (q0 == jb + 8 ? 0x3F80u : 0u) | (q0 == jb + 9 ? 0x3F800000u : 0u);
            A1[4 * kt + 3] = (q1 == jb + 8 ? 0x3F80u : 0u) | (q1 == jb + 9 ? 0x3F800000u : 0u);
        }
    }

    float D[8][4];
#pragma unroll
    for (int nt = 0; nt < 8; nt++) {
        float d0 = 0.f, d1 = 0.f, d2 = 0.f, d3 = 0.f;
#pragma unroll
        for (int kt = 0; kt < 8; kt++) {
            const u64 bh = s_B1h[(kt * 8 + nt) * 32 + lane];
            const u64 bl = s_B1l[(kt * 8 + nt) * 32 + lane];
            MMA4(d0,d1,d2,d3, A1[4*kt],A1[4*kt+1],A1[4*kt+2],A1[4*kt+3], (u32)bh, (u32)(bh >> 32));
            MMA4(d0,d1,d2,d3, A1[4*kt],A1[4*kt+1],A1[4*kt+2],A1[4*kt+3], (u32)bl, (u32)(bl >> 32));
        }
        D[nt][0] = fmaxf(d0, 0.f); D[nt][1] = fmaxf(d1, 0.f);
        D[nt][2] = fmaxf(d2, 0.f); D[nt][3] = fmaxf(d3, 0.f);
    }

    // D -> layer2 A frags (hi/lo), in-register
    u32 ah[16], al[16];
#pragma unroll
    for (int kt = 0; kt < 4; kt++) {
        const float e0 = D[2*kt][0],   e1 = D[2*kt][1];
        const float e2 = D[2*kt][2],   e3 = D[2*kt][3];
        const float f0 = D[2*kt+1][0], f1 = D[2*kt+1][1];
        const float f2 = D[2*kt+1][2], f3 = D[2*kt+1][3];
        u32 h;
        CVTP(h, e1, e0); ah[4*kt+0] = h;
        { float g0 = e0 - __uint_as_float(h << 16), g1 = e1 - __uint_as_float(h & 0xFFFF0000u); CVTP(al[4*kt+0], g1, g0); }
        CVTP(h, e3, e2); ah[4*kt+1] = h;
        { float g0 = e2 - __uint_as_float(h << 16), g1 = e3 - __uint_as_float(h & 0xFFFF0000u); CVTP(al[4*kt+1], g1, g0); }
        CVTP(h, f1, f0); ah[4*kt+2] = h;
        { float g0 = f0 - __uint_as_float(h << 16), g1 = f1 - __uint_as_float(h & 0xFFFF0000u); CVTP(al[4*kt+2], g1, g0); }
        CVTP(h, f3, f2); ah[4*kt+3] = h;
        { float g0 = f2 - __uint_as_float(h << 16), g1 = f3 - __uint_as_float(h & 0xFFFF0000u); CVTP(al[4*kt+3], g1, g0); }
    }

    // layer2: 3-term bf16 GEMM
    const int item0 = blockIdx.x * 128 + r0i;
#pragma unroll
    for (int nt = 0; nt < 8; nt++) {
        float d0 = 0.f, d1 = 0.f, d2 = 0.f, d3 = 0.f;
#pragma unroll
        for (int kt = 0; kt < 4; kt++) {
            const u64 bh = s_B2h[(kt * 8 + nt) * 32 + lane];
            const u64 bl = s_B2l[(kt * 8 + nt) * 32 + lane];
            const u32 bh0 = (u32)bh, bh1 = (u32)(bh >> 32);
            const u32 bl0 = (u32)bl, bl1 = (u32)(bl >> 32);
            MMA4(d0,d1,d2,d3, ah[4*kt],ah[4*kt+1],ah[4*kt+2],ah[4*kt+3], bh0,bh1);
            MMA4(d0,d1,d2,d3, ah[4*kt],ah[4*kt+1],ah[4*kt+2],ah[4*kt+3], bl0,bl1);
            MMA4(d0,d1,d2,d3, al[4*kt],al[4*kt+1],al[4*kt+2],al[4*kt+3], bh0,bh1);
        }
        const int c0 = nt * 8 + (lane & 3) * 2;
        const float bb0 = s_b2[c0], bb1 = s_b2[c0 + 1];
        *(float2*)(out + (size_t)item0 * 64 + c0)       = make_float2(d0 + bb0, d1 + bb1);
        *(float2*)(out + (size_t)(item0 + 8) * 64 + c0) = make_float2(d2 + bb0, d3 + bb1);
    }
}

// ---------------------------------------------------------------------------
extern "C" void kernel_launch(void* const* d_in, const int* in_sizes, int n_in,
                              void* d_out, int out_size)
{
    const int*   seqs = (const int*)  d_in[0];
    const int*   qtok = (const int*)  d_in[1];
    const float* emb  = (const float*)d_in[2];
    const float* sw1  = (const float*)d_in[3];
    const float* sb1  = (const float*)d_in[4];
    const float* sw2  = (const float*)d_in[5];
    const float* sb2  = (const float*)d_in[6];
    const float* w1   = (const float*)d_in[7];
    const float* b1   = (const float*)d_in[8];
    const float* w2   = (const float*)d_in[9];
    const float* b2   = (const float*)d_in[10];
    float* out = (float*)d_out;

    cudaFuncSetAttribute(main_k, cudaFuncAttributeMaxDynamicSharedMemorySize, SMEM_TOTAL);

    prep_k<<<11, 256>>>(emb, sw1, sb1, sw2, sb2, w1, b1, w2);
    main_k<<<NB / 128, 256, SMEM_TOTAL>>>(seqs, qtok, b2, out);
}

// round 15
// speedup vs baseline: 1.1651x; 1.1651x over previous
#include <cuda_runtime.h>

#define NB      32768
#define SLOTS   8

__device__ float g_score[64];
__device__ float g_Q1[64 * 64];   // embed[t] @ rh_w1[0:64] + rh_b1
__device__ float g_E1[64 * 64];   // (1/8) * embed[t] @ rh_w1[64:128]

typedef unsigned long long u64;
typedef unsigned int u32;

__device__ u64 g_Bh[1024];        // W2 hi-bf16 mma B-fragments [tile=kt*8+nt][lane]
__device__ u64 g_Bl[1024];        // W2 lo-bf16 fragments

#define ADD2T(d, x, y)     asm("add.rn.f32x2 %0, %1, %2;" : "=l"(d) : "l"(x), "l"(y))
#define UNPACK2(lo, hi, s) asm("mov.b64 {%0, %1}, %2;" : "=f"(lo), "=f"(hi) : "l"(s))
#define CVTP(d, fhi, flo)  asm("cvt.rn.bf16x2.f32 %0, %1, %2;" : "=r"(d) : "f"(fhi), "f"(flo))
#define MMA4(d0,d1,d2,d3,a0,a1,a2,a3,b0,b1) \
    asm("mma.sync.aligned.m16n8k16.row.col.f32.bf16.bf16.f32 " \
        "{%0,%1,%2,%3},{%4,%5,%6,%7},{%8,%9},{%0,%1,%2,%3};" \
        : "+f"(d0),"+f"(d1),"+f"(d2),"+f"(d3) \
        : "r"(a0),"r"(a1),"r"(a2),"r"(a3),"r"(b0),"r"(b1))

// main_k smem layout (bytes) — r11 layout verbatim
#define OFF_E1   0          // float[64*68]  = 17408
#define OFF_AHI  17408      // u32[128*36]   = 18432
#define OFF_ALO  35840      // u32[128*36]   = 18432
#define OFF_BH   54272      // u64[1024]     = 8192
#define OFF_BL   62464      // u64[1024]     = 8192
#define OFF_SC   70656      // float[64]
#define OFF_B2   70912      // float[64]
#define OFF_TOK  71168      // u64[128]
#define OFF_Q    72192      // int[128]
#define OFF_RK   72704      // u32[64]
#define SMEM_TOTAL 72960

static __device__ __forceinline__ void split_pack(
    float f00, float f01, float f10, float f11, u64* ph, u64* pl)
{
    u32 b0h, b1h, b0l, b1l;
    CVTP(b0h, f01, f00);
    CVTP(b1h, f11, f10);
    const float h00 = __uint_as_float(b0h << 16), h01 = __uint_as_float(b0h & 0xFFFF0000u);
    const float h10 = __uint_as_float(b1h << 16), h11 = __uint_as_float(b1h & 0xFFFF0000u);
    CVTP(b0l, f01 - h01, f00 - h00);
    CVTP(b1l, f11 - h11, f10 - h10);
    *ph = (u64)b0h | ((u64)b1h << 32);
    *pl = (u64)b0l | ((u64)b1l << 32);
}

// ---------------------------------------------------------------------------
// prep_k: ONE kernel, 11 blocks x 256 threads.
//  blocks 0-3: E1 rows for tokens b*16..b*16+15
//  blocks 4-7: Q1 rows for tokens (b-4)*16..+15
//  blocks 8-9: B2 fragments from w2
//  block  10 : score table
// ---------------------------------------------------------------------------
__global__ void __launch_bounds__(256) prep_k(
    const float* __restrict__ emb,
    const float* __restrict__ sw1, const float* __restrict__ sb1,
    const float* __restrict__ sw2, const float* __restrict__ sb2,
    const float* __restrict__ w1,  const float* __restrict__ b1,
    const float* __restrict__ w2)
{
    __shared__ float sbuf[64 * 64];          // 16KB
    const int tid = threadIdx.x;
    const int b   = blockIdx.x;

    if (b < 8) {
        float* s_emb = sbuf;                 // [16][64]
        const int kt = b;
        const int base_tok = (kt < 4) ? kt * 16 : (kt - 4) * 16;
        ((float4*)s_emb)[tid] = ((const float4*)(emb + base_tok * 64))[tid];
        __syncthreads();

        const int r = tid >> 4, n0 = (tid & 15) * 4;
        const int off = (kt < 4) ? 64 : 0;   // E1 uses w1[64+d], Q1 uses w1[d]
        float a0 = 0.f, a1 = 0.f, a2 = 0.f, a3 = 0.f;
#pragma unroll 8
        for (int d = 0; d < 64; d++) {
            const float e = s_emb[r * 64 + d];
            const float4 wv = *(const float4*)(w1 + (off + d) * 64 + n0);
            a0 = fmaf(e, wv.x, a0); a1 = fmaf(e, wv.y, a1);
            a2 = fmaf(e, wv.z, a2); a3 = fmaf(e, wv.w, a3);
        }
        if (kt < 4) {
            a0 *= 0.125f; a1 *= 0.125f; a2 *= 0.125f; a3 *= 0.125f;
            *(float4*)(g_E1 + (base_tok + r) * 64 + n0) = make_float4(a0, a1, a2, a3);
        } else {
            a0 += b1[n0]; a1 += b1[n0 + 1]; a2 += b1[n0 + 2]; a3 += b1[n0 + 3];
            *(float4*)(g_Q1 + (base_tok + r) * 64 + n0) = make_float4(a0, a1, a2, a3);
        }
        return;
    }

    if (b < 10) {
        // B2 fragments (validated mapping)
#pragma unroll
        for (int j = 0; j < 2; j++) {
            const int e = (b - 8) * 512 + tid * 2 + j;
            const int tile = e >> 5, l = e & 31;
            const int kt = tile >> 3, nt = tile & 7;
            const int k0 = kt * 16 + (l & 3) * 2;
            const int n  = nt * 8 + (l >> 2);
            split_pack(w2[k0 * 64 + n], w2[(k0 + 1) * 64 + n],
                       w2[(k0 + 8) * 64 + n], w2[(k0 + 9) * 64 + n],
                       &g_Bh[e], &g_Bl[e]);
        }
        return;
    }

    // block 10: score table
#pragma unroll
    for (int i = tid; i < 1024; i += 256)
        ((float4*)sbuf)[i] = ((const float4*)emb)[i];
    __syncthreads();
    {
        const int tok = tid >> 2, p = tid & 3;
        float acc[8];
#pragma unroll
        for (int h = 0; h < 8; h++) acc[h] = sb1[p * 8 + h];
#pragma unroll 4
        for (int d = 0; d < 64; d++) {
            const float e = sbuf[tok * 64 + d];
            const float4 wa = *(const float4*)(sw1 + d * 32 + p * 8);
            const float4 wb = *(const float4*)(sw1 + d * 32 + p * 8 + 4);
            acc[0] = fmaf(e, wa.x, acc[0]); acc[1] = fmaf(e, wa.y, acc[1]);
            acc[2] = fmaf(e, wa.z, acc[2]); acc[3] = fmaf(e, wa.w, acc[3]);
            acc[4] = fmaf(e, wb.x, acc[4]); acc[5] = fmaf(e, wb.y, acc[5]);
            acc[6] = fmaf(e, wb.z, acc[6]); acc[7] = fmaf(e, wb.w, acc[7]);
        }
        float s = 0.f;
#pragma unroll
        for (int h = 0; h < 8; h++) s += fmaxf(acc[h], 0.f) * sw2[p * 8 + h];
        s += __shfl_down_sync(0xffffffffu, s, 2, 4);
        s += __shfl_down_sync(0xffffffffu, s, 1, 4);
        if (p == 0) g_score[tok] = s + sb2[0];
    }
}

// ---------------------------------------------------------------------------
// main_k: round-11 version VERBATIM (proven 12.7us, rel_err 2.47e-6).
// ---------------------------------------------------------------------------
__global__ void __launch_bounds__(256, 2) main_k(
    const int*   __restrict__ seqs,
    const int*   __restrict__ qtok,
    const float* __restrict__ b2,
    float*       __restrict__ out)
{
    extern __shared__ __align__(16) char dyn[];
    float* s_E1  = (float*)(dyn + OFF_E1);
    u64*   s_Ahi = (u64*)(dyn + OFF_AHI);
    u64*   s_Alo = (u64*)(dyn + OFF_ALO);
    u64*   s_Bh  = (u64*)(dyn + OFF_BH);
    u64*   s_Bl  = (u64*)(dyn + OFF_BL);
    float* s_sc  = (float*)(dyn + OFF_SC);
    float* s_b2  = (float*)(dyn + OFF_B2);
    u64*   s_tok = (u64*)(dyn + OFF_TOK);
    int*   s_q   = (int*)(dyn + OFF_Q);
    u32*   s_rk  = (u32*)(dyn + OFF_RK);

    const int tid = threadIdx.x;

    if (tid < 64) { s_sc[tid] = g_score[tid]; s_b2[tid] = b2[tid]; }
    __syncthreads();

    if (tid >= 64 && tid < 128) {
        const int t = tid - 64;
        const float st = s_sc[t];
        int r = 0;
#pragma unroll 16
        for (int u = 0; u < 64; u++) r += (s_sc[u] < st);
        s_rk[t] = ((u32)r << 11) | (u32)t;
    }
    __syncthreads();

    if (tid < 128) {
        // ---- eviction scan (integer keys) ----
        const int item = blockIdx.x * 128 + tid;
        const int4* sp = (const int4*)seqs + item * 8;
        u32 w8[8];
#pragma unroll
        for (int g = 0; g < 8; g++) {
            const int4 v = sp[g];
            w8[g] = (u32)(v.x & 63) | ((u32)(v.y & 63) << 8) |
                    ((u32)(v.z & 63) << 16) | ((u32)(v.w & 63) << 24);
        }
        u32 k31[31];
#pragma unroll
        for (int j = 0; j < 31; j++) {
            const u32 t = (w8[j >> 2] >> ((j & 3) * 8)) & 63u;
            k31[j] = s_rk[t] + ((u32)j << 6);
        }
        u32 key[SLOTS];
#pragma unroll
        for (int j = 0; j < SLOTS; j++) key[j] = k31[j];
#pragma unroll
        for (int step = 8; step < 31; step++) {
            const u32 m01 = umin(key[0], key[1]);
            const u32 m23 = umin(key[2], key[3]);
            const u32 m45 = umin(key[4], key[5]);
            const u32 m67 = umin(key[6], key[7]);
            const u32 mk  = umin(umin(m01, m23), umin(m45, m67));
            const u32 nk  = k31[step];
#pragma unroll
            for (int j = 0; j < SLOTS; j++)
                key[j] = (key[j] == mk) ? nk : key[j];
        }
        u64 t8 = 0;
#pragma unroll
        for (int s = 0; s < SLOTS; s++) t8 |= (u64)(key[s] & 63u) << (8 * s);
        s_tok[tid] = t8;
        s_q[tid]   = qtok[item] & 63;
    } else {
        // ---- staging: E1 table + B fragments (overlapped with scan) ----
        const int t2 = tid - 128;
#pragma unroll
        for (int i4 = t2; i4 < 1024; i4 += 128) {
            const float4 e = ((const float4*)g_E1)[i4];
            *(float4*)(s_E1 + (i4 >> 4) * 68 + (i4 & 15) * 4) = e;
        }
#pragma unroll
        for (int i = t2; i < 512; i += 128) {
            ((ulonglong2*)s_Bh)[i] = ((const ulonglong2*)g_Bh)[i];
            ((ulonglong2*)s_Bl)[i] = ((const ulonglong2*)g_Bl)[i];
        }
    }
    __syncthreads();

    // ---- gather: layer1 tree-adds -> bf16 hi/lo A fragments (all 128 items) ----
    {
        const int lane = tid & 31;
        const int wrp  = tid >> 5;
        const int o4   = lane & 15;
        const int hi16 = lane >> 4;
        const ulonglong2* E1q = (const ulonglong2*)s_E1;
        const ulonglong2* Q1q = (const ulonglong2*)g_Q1;
#pragma unroll
        for (int p = 0; p < 8; p++) {
            const int it = wrp * 16 + 2 * p + hi16;
            const u64 t8 = s_tok[it];
            const int q  = s_q[it];
            const ulonglong2 qv = Q1q[q * 16 + o4];
            ulonglong2 ev[SLOTS];
#pragma unroll
            for (int s = 0; s < SLOTS; s++)
                ev[s] = E1q[((int)((t8 >> (8 * s)) & 63)) * 17 + o4];
            u64 x0, x1, x2, x3, y0, y1, z0, P0, P1;
            ADD2T(x0, ev[0].x, ev[1].x); ADD2T(x1, ev[2].x, ev[3].x);
            ADD2T(x2, ev[4].x, ev[5].x); ADD2T(x3, ev[6].x, ev[7].x);
            ADD2T(y0, x0, x1); ADD2T(y1, x2, x3);
            ADD2T(z0, y0, y1); ADD2T(P0, z0, qv.x);
            ADD2T(x0, ev[0].y, ev[1].y); ADD2T(x1, ev[2].y, ev[3].y);
            ADD2T(x2, ev[4].y, ev[5].y); ADD2T(x3, ev[6].y, ev[7].y);
            ADD2T(y0, x0, x1); ADD2T(y1, x2, x3);
            ADD2T(z0, y0, y1); ADD2T(P1, z0, qv.y);

            float f0, f1, f2, f3;
            UNPACK2(f0, f1, P0); UNPACK2(f2, f3, P1);
            f0 = fmaxf(f0, 0.0f); f1 = fmaxf(f1, 0.0f);
            f2 = fmaxf(f2, 0.0f); f3 = fmaxf(f3, 0.0f);
            u32 h0, h1, l0, l1;
            CVTP(h0, f1, f0);
            CVTP(h1, f3, f2);
            const float hf0 = __uint_as_float(h0 << 16), hf1 = __uint_as_float(h0 & 0xFFFF0000u);
            const float hf2 = __uint_as_float(h1 << 16), hf3 = __uint_as_float(h1 & 0xFFFF0000u);
            CVTP(l0, f1 - hf1, f0 - hf0);
            CVTP(l1, f3 - hf3, f2 - hf2);
            s_Ahi[it * 18 + o4] = (u64)h0 | ((u64)h1 << 32);
            s_Alo[it * 18 + o4] = (u64)l0 | ((u64)l1 << 32);
        }
    }
    __syncthreads();

    // ---- layer2: mma.sync bf16 3-term GEMM (8 warps, warp = m-block) ----
    {
        const int lane = tid & 31;
        const int mb   = tid >> 5;
        const int r0   = mb * 16 + (lane >> 2);
        const u32* Ah = (const u32*)s_Ahi;
        const u32* Al = (const u32*)s_Alo;

        u32 ah[16], al[16];
#pragma unroll
        for (int kt = 0; kt < 4; kt++) {
            const int kp = kt * 8 + (lane & 3);
            ah[4 * kt + 0] = Ah[r0 * 36 + kp];
            ah[4 * kt + 1] = Ah[(r0 + 8) * 36 + kp];
            ah[4 * kt + 2] = Ah[r0 * 36 + kp + 4];
            ah[4 * kt + 3] = Ah[(r0 + 8) * 36 + kp + 4];
            al[4 * kt + 0] = Al[r0 * 36 + kp];
            al[4 * kt + 1] = Al[(r0 + 8) * 36 + kp];
            al[4 * kt + 2] = Al[r0 * 36 + kp + 4];
            al[4 * kt + 3] = Al[(r0 + 8) * 36 + kp + 4];
        }

        const int item0 = blockIdx.x * 128 + r0;
#pragma unroll
        for (int nt = 0; nt < 8; nt++) {
            float d0 = 0.f, d1 = 0.f, d2 = 0.f, d3 = 0.f;
#pragma unroll
            for (int kt = 0; kt < 4; kt++) {
                const u64 bh = s_Bh[(kt * 8 + nt) * 32 + lane];
                const u64 bl = s_Bl[(kt * 8 + nt) * 32 + lane];
                const u32 bh0 = (u32)bh, bh1 = (u32)(bh >> 32);
                const u32 bl0 = (u32)bl, bl1 = (u32)(bl >> 32);
                MMA4(d0,d1,d2,d3, ah[4*kt],ah[4*kt+1],ah[4*kt+2],ah[4*kt+3], bh0,bh1);
                MMA4(d0,d1,d2,d3, ah[4*kt],ah[4*kt+1],ah[4*kt+2],ah[4*kt+3], bl0,bl1);
                MMA4(d0,d1,d2,d3, al[4*kt],al[4*kt+1],al[4*kt+2],al[4*kt+3], bh0,bh1);
            }
            const int c0 = nt * 8 + (lane & 3) * 2;
            const float bb0 = s_b2[c0], bb1 = s_b2[c0 + 1];
            *(float2*)(out + (size_t)item0 * 64 + c0)       = make_float2(d0 + bb0, d1 + bb1);
            *(float2*)(out + (size_t)(item0 + 8) * 64 + c0) = make_float2(d2 + bb0, d3 + bb1);
        }
    }
}

// ---------------------------------------------------------------------------
extern "C" void kernel_launch(void* const* d_in, const int* in_sizes, int n_in,
                              void* d_out, int out_size)
{
    const int*   seqs = (const int*)  d_in[0];
    const int*   qtok = (const int*)  d_in[1];
    const float* emb  = (const float*)d_in[2];
    const float* sw1  = (const float*)d_in[3];
    const float* sb1  = (const float*)d_in[4];
    const float* sw2  = (const float*)d_in[5];
    const float* sb2  = (const float*)d_in[6];
    const float* w1   = (const float*)d_in[7];
    const float* b1   = (const float*)d_in[8];
    const float* w2   = (const float*)d_in[9];
    const float* b2   = (const float*)d_in[10];
    float* out = (float*)d_out;

    cudaFuncSetAttribute(main_k, cudaFuncAttributeMaxDynamicSharedMemorySize, SMEM_TOTAL);

    prep_k<<<11, 256>>>(emb, sw1, sb1, sw2, sb2, w1, b1, w2);
    main_k<<<NB / 128, 256, SMEM_TOTAL>>>(seqs, qtok, b2, out);
}

// round 16
// speedup vs baseline: 1.5832x; 1.3589x over previous
#include <cuda_runtime.h>

#define NB      32768
#define SLOTS   8
#define ITEMS   224
#define THREADS 448

__device__ float g_score[64];
__device__ float g_Q1[64 * 64];   // embed[t] @ rh_w1[0:64] + rh_b1
__device__ float g_E1[64 * 64];   // (1/8) * embed[t] @ rh_w1[64:128]

typedef unsigned long long u64;
typedef unsigned int u32;

__device__ u64 g_Bh[1024];        // W2 hi-bf16 mma B-fragments [tile=kt*8+nt][lane]
__device__ u64 g_Bl[1024];        // W2 lo-bf16 fragments

#define ADD2T(d, x, y)     asm("add.rn.f32x2 %0, %1, %2;" : "=l"(d) : "l"(x), "l"(y))
#define UNPACK2(lo, hi, s) asm("mov.b64 {%0, %1}, %2;" : "=f"(lo), "=f"(hi) : "l"(s))
#define CVTP(d, fhi, flo)  asm("cvt.rn.bf16x2.f32 %0, %1, %2;" : "=r"(d) : "f"(fhi), "f"(flo))
#define MMA4(d0,d1,d2,d3,a0,a1,a2,a3,b0,b1) \
    asm("mma.sync.aligned.m16n8k16.row.col.f32.bf16.bf16.f32 " \
        "{%0,%1,%2,%3},{%4,%5,%6,%7},{%8,%9},{%0,%1,%2,%3};" \
        : "+f"(d0),"+f"(d1),"+f"(d2),"+f"(d3) \
        : "r"(a0),"r"(a1),"r"(a2),"r"(a3),"r"(b0),"r"(b1))

// main_k smem layout (bytes) — 224-item tile
#define OFF_E1   0          // float[64*68]   = 17408
#define OFF_AHI  17408      // u32[224*36]    = 32256
#define OFF_ALO  49664      // u32[224*36]    = 32256
#define OFF_BH   81920      // u64[1024]      = 8192
#define OFF_BL   90112      // u64[1024]      = 8192
#define OFF_SC   98304      // float[64]
#define OFF_B2   98560      // float[64]
#define OFF_TOK  98816      // u64[224]       = 1792
#define OFF_Q    100608     // int[224]       = 896
#define OFF_RK   101504     // u32[64]        = 256
#define SMEM_TOTAL 101760

static __device__ __forceinline__ void split_pack(
    float f00, float f01, float f10, float f11, u64* ph, u64* pl)
{
    u32 b0h, b1h, b0l, b1l;
    CVTP(b0h, f01, f00);
    CVTP(b1h, f11, f10);
    const float h00 = __uint_as_float(b0h << 16), h01 = __uint_as_float(b0h & 0xFFFF0000u);
    const float h10 = __uint_as_float(b1h << 16), h11 = __uint_as_float(b1h & 0xFFFF0000u);
    CVTP(b0l, f01 - h01, f00 - h00);
    CVTP(b1l, f11 - h11, f10 - h10);
    *ph = (u64)b0h | ((u64)b1h << 32);
    *pl = (u64)b0l | ((u64)b1l << 32);
}

// ---------------------------------------------------------------------------
// precompute (r11 structure verbatim: 72 blocks x 128 — wide for latency hiding)
//  blocks 0-63: tables (E1/Q1/score), blocks 64-71: B2 fragments
// ---------------------------------------------------------------------------
__global__ void __launch_bounds__(128) precompute_k(
    const float* __restrict__ emb,
    const float* __restrict__ sw1, const float* __restrict__ sb1,
    const float* __restrict__ sw2, const float* __restrict__ sb2,
    const float* __restrict__ w1,  const float* __restrict__ b1,
    const float* __restrict__ w2)
{
    const int tid = threadIdx.x;
    if (blockIdx.x >= 64) {
        const int e = (blockIdx.x - 64) * 128 + tid;
        if (e < 1024) {
            const int tile = e >> 5, l = e & 31;
            const int kt = tile >> 3, nt = tile & 7;
            const int k0 = kt * 16 + (l & 3) * 2;
            const int n  = nt * 8 + (l >> 2);
            split_pack(w2[k0 * 64 + n], w2[(k0 + 1) * 64 + n],
                       w2[(k0 + 8) * 64 + n], w2[(k0 + 9) * 64 + n],
                       &g_Bh[e], &g_Bl[e]);
        }
        return;
    }

    const int t = blockIdx.x;
    __shared__ float s_e[64];
    if (tid < 16) ((float4*)s_e)[tid] = ((const float4*)(emb + t * 64))[tid];
    __syncthreads();

    const int half = tid >> 6;
    const int o    = tid & 63;
    const float* wcol = w1 + half * 64 * 64 + o;
    float acc = half ? 0.0f : b1[o];
#pragma unroll
    for (int k = 0; k < 64; k++) acc = fmaf(s_e[k], wcol[k * 64], acc);
    if (half) g_E1[t * 64 + o] = acc * 0.125f;
    else      g_Q1[t * 64 + o] = acc;

    if (tid < 32) {
        float h = sb1[tid];
#pragma unroll
        for (int d = 0; d < 64; d++) h = fmaf(s_e[d], sw1[d * 32 + tid], h);
        float p = fmaxf(h, 0.0f) * sw2[tid];
#pragma unroll
        for (int off = 16; off > 0; off >>= 1)
            p += __shfl_down_sync(0xffffffffu, p, off);
        if (tid == 0) g_score[t] = p + sb2[0];
    }
}

// ---------------------------------------------------------------------------
// main_k: 147 CTAs x 448 threads (14 warps), 224 items/CTA — 1 CTA/SM,
// single balanced wave. Logic identical to proven r11/r15 main, re-tiled.
// ---------------------------------------------------------------------------
__global__ void __launch_bounds__(THREADS, 1) main_k(
    const int*   __restrict__ seqs,
    const int*   __restrict__ qtok,
    const float* __restrict__ b2,
    float*       __restrict__ out)
{
    extern __shared__ __align__(16) char dyn[];
    float* s_E1  = (float*)(dyn + OFF_E1);
    u64*   s_Ahi = (u64*)(dyn + OFF_AHI);
    u64*   s_Alo = (u64*)(dyn + OFF_ALO);
    u64*   s_Bh  = (u64*)(dyn + OFF_BH);
    u64*   s_Bl  = (u64*)(dyn + OFF_BL);
    float* s_sc  = (float*)(dyn + OFF_SC);
    float* s_b2  = (float*)(dyn + OFF_B2);
    u64*   s_tok = (u64*)(dyn + OFF_TOK);
    int*   s_q   = (int*)(dyn + OFF_Q);
    u32*   s_rk  = (u32*)(dyn + OFF_RK);

    const int tid  = threadIdx.x;
    const int base = min((int)blockIdx.x * ITEMS, NB - ITEMS);  // overlap-pad last tile

    if (tid < 64) { s_sc[tid] = g_score[tid]; s_b2[tid] = b2[tid]; }
    __syncthreads();

    if (tid >= 64 && tid < 128) {
        const int t = tid - 64;
        const float st = s_sc[t];
        int r = 0;
#pragma unroll 16
        for (int u = 0; u < 64; u++) r += (s_sc[u] < st);
        s_rk[t] = ((u32)r << 11) | (u32)t;
    }
    __syncthreads();

    if (tid < ITEMS) {
        // ---- eviction scan (integer keys) ----
        const int item = base + tid;
        const int4* sp = (const int4*)seqs + item * 8;
        u32 w8[8];
#pragma unroll
        for (int g = 0; g < 8; g++) {
            const int4 v = sp[g];
            w8[g] = (u32)(v.x & 63) | ((u32)(v.y & 63) << 8) |
                    ((u32)(v.z & 63) << 16) | ((u32)(v.w & 63) << 24);
        }
        u32 k31[31];
#pragma unroll
        for (int j = 0; j < 31; j++) {
            const u32 t = (w8[j >> 2] >> ((j & 3) * 8)) & 63u;
            k31[j] = s_rk[t] + ((u32)j << 6);
        }
        u32 key[SLOTS];
#pragma unroll
        for (int j = 0; j < SLOTS; j++) key[j] = k31[j];
#pragma unroll
        for (int step = 8; step < 31; step++) {
            const u32 m01 = umin(key[0], key[1]);
            const u32 m23 = umin(key[2], key[3]);
            const u32 m45 = umin(key[4], key[5]);
            const u32 m67 = umin(key[6], key[7]);
            const u32 mk  = umin(umin(m01, m23), umin(m45, m67));
            const u32 nk  = k31[step];
#pragma unroll
            for (int j = 0; j < SLOTS; j++)
                key[j] = (key[j] == mk) ? nk : key[j];
        }
        u64 t8 = 0;
#pragma unroll
        for (int s = 0; s < SLOTS; s++) t8 |= (u64)(key[s] & 63u) << (8 * s);
        s_tok[tid] = t8;
        s_q[tid]   = qtok[item] & 63;
    } else {
        // ---- staging: E1 table + B fragments (overlapped with scan) ----
        const int t2 = tid - ITEMS;                 // 0..223
        for (int i4 = t2; i4 < 1024; i4 += ITEMS) {
            const float4 e = ((const float4*)g_E1)[i4];
            *(float4*)(s_E1 + (i4 >> 4) * 68 + (i4 & 15) * 4) = e;
        }
        for (int i = t2; i < 512; i += ITEMS) {
            ((ulonglong2*)s_Bh)[i] = ((const ulonglong2*)g_Bh)[i];
            ((ulonglong2*)s_Bl)[i] = ((const ulonglong2*)g_Bl)[i];
        }
    }
    __syncthreads();

    // ---- gather: layer1 tree-adds -> bf16 hi/lo A fragments (14 warps x 16 items) ----
    {
        const int lane = tid & 31;
        const int wrp  = tid >> 5;
        const int o4   = lane & 15;
        const int hi16 = lane >> 4;
        const ulonglong2* E1q = (const ulonglong2*)s_E1;
        const ulonglong2* Q1q = (const ulonglong2*)g_Q1;
#pragma unroll
        for (int p = 0; p < 8; p++) {
            const int it = wrp * 16 + 2 * p + hi16;
            const u64 t8 = s_tok[it];
            const int q  = s_q[it];
            const ulonglong2 qv = Q1q[q * 16 + o4];
            ulonglong2 ev[SLOTS];
#pragma unroll
            for (int s = 0; s < SLOTS; s++)
                ev[s] = E1q[((int)((t8 >> (8 * s)) & 63)) * 17 + o4];
            u64 x0, x1, x2, x3, y0, y1, z0, P0, P1;
            ADD2T(x0, ev[0].x, ev[1].x); ADD2T(x1, ev[2].x, ev[3].x);
            ADD2T(x2, ev[4].x, ev[5].x); ADD2T(x3, ev[6].x, ev[7].x);
            ADD2T(y0, x0, x1); ADD2T(y1, x2, x3);
            ADD2T(z0, y0, y1); ADD2T(P0, z0, qv.x);
            ADD2T(x0, ev[0].y, ev[1].y); ADD2T(x1, ev[2].y, ev[3].y);
            ADD2T(x2, ev[4].y, ev[5].y); ADD2T(x3, ev[6].y, ev[7].y);
            ADD2T(y0, x0, x1); ADD2T(y1, x2, x3);
            ADD2T(z0, y0, y1); ADD2T(P1, z0, qv.y);

            float f0, f1, f2, f3;
            UNPACK2(f0, f1, P0); UNPACK2(f2, f3, P1);
            f0 = fmaxf(f0, 0.0f); f1 = fmaxf(f1, 0.0f);
            f2 = fmaxf(f2, 0.0f); f3 = fmaxf(f3, 0.0f);
            u32 h0, h1, l0, l1;
            CVTP(h0, f1, f0);
            CVTP(h1, f3, f2);
            const float hf0 = __uint_as_float(h0 << 16), hf1 = __uint_as_float(h0 & 0xFFFF0000u);
            const float hf2 = __uint_as_float(h1 << 16), hf3 = __uint_as_float(h1 & 0xFFFF0000u);
            CVTP(l0, f1 - hf1, f0 - hf0);
            CVTP(l1, f3 - hf3, f2 - hf2);
            s_Ahi[it * 18 + o4] = (u64)h0 | ((u64)h1 << 32);
            s_Alo[it * 18 + o4] = (u64)l0 | ((u64)l1 << 32);
        }
    }
    __syncthreads();

    // ---- layer2: mma.sync bf16 3-term GEMM (warp = m-block, 14 m-blocks) ----
    {
        const int lane = tid & 31;
        const int mb   = tid >> 5;                  // 0..13
        const int r0   = mb * 16 + (lane >> 2);
        const u32* Ah = (const u32*)s_Ahi;
        const u32* Al = (const u32*)s_Alo;

        u32 ah[16], al[16];
#pragma unroll
        for (int kt = 0; kt < 4; kt++) {
            const int kp = kt * 8 + (lane & 3);
            ah[4 * kt + 0] = Ah[r0 * 36 + kp];
            ah[4 * kt + 1] = Ah[(r0 + 8) * 36 + kp];
            ah[4 * kt + 2] = Ah[r0 * 36 + kp + 4];
            ah[4 * kt + 3] = Ah[(r0 + 8) * 36 + kp + 4];
            al[4 * kt + 0] = Al[r0 * 36 + kp];
            al[4 * kt + 1] = Al[(r0 + 8) * 36 + kp];
            al[4 * kt + 2] = Al[r0 * 36 + kp + 4];
            al[4 * kt + 3] = Al[(r0 + 8) * 36 + kp + 4];
        }

        const int item0 = base + r0;
#pragma unroll
        for (int nt = 0; nt < 8; nt++) {
            float d0 = 0.f, d1 = 0.f, d2 = 0.f, d3 = 0.f;
#pragma unroll
            for (int kt = 0; kt < 4; kt++) {
                const u64 bh = s_Bh[(kt * 8 + nt) * 32 + lane];
                const u64 bl = s_Bl[(kt * 8 + nt) * 32 + lane];
                const u32 bh0 = (u32)bh, bh1 = (u32)(bh >> 32);
                const u32 bl0 = (u32)bl, bl1 = (u32)(bl >> 32);
                MMA4(d0,d1,d2,d3, ah[4*kt],ah[4*kt+1],ah[4*kt+2],ah[4*kt+3], bh0,bh1);
                MMA4(d0,d1,d2,d3, ah[4*kt],ah[4*kt+1],ah[4*kt+2],ah[4*kt+3], bl0,bl1);
                MMA4(d0,d1,d2,d3, al[4*kt],al[4*kt+1],al[4*kt+2],al[4*kt+3], bh0,bh1);
            }
            const int c0 = nt * 8 + (lane & 3) * 2;
            const float bb0 = s_b2[c0], bb1 = s_b2[c0 + 1];
            *(float2*)(out + (size_t)item0 * 64 + c0)       = make_float2(d0 + bb0, d1 + bb1);
            *(float2*)(out + (size_t)(item0 + 8) * 64 + c0) = make_float2(d2 + bb0, d3 + bb1);
        }
    }
}

// ---------------------------------------------------------------------------
extern "C" void kernel_launch(void* const* d_in, const int* in_sizes, int n_in,
                              void* d_out, int out_size)
{
    const int*   seqs = (const int*)  d_in[0];
    const int*   qtok = (const int*)  d_in[1];
    const float* emb  = (const float*)d_in[2];
    const float* sw1  = (const float*)d_in[3];
    const float* sb1  = (const float*)d_in[4];
    const float* sw2  = (const float*)d_in[5];
    const float* sb2  = (const float*)d_in[6];
    const float* w1   = (const float*)d_in[7];
    const float* b1   = (const float*)d_in[8];
    const float* w2   = (const float*)d_in[9];
    const float* b2   = (const float*)d_in[10];
    float* out = (float*)d_out;

    cudaFuncSetAttribute(main_k, cudaFuncAttributeMaxDynamicSharedMemorySize, SMEM_TOTAL);

    precompute_k<<<72, 128>>>(emb, sw1, sb1, sw2, sb2, w1, b1, w2);
    const int grid = (NB + ITEMS - 1) / ITEMS;      // 147
    main_k<<<grid, THREADS, SMEM_TOTAL>>>(seqs, qtok, b2, out);
}